// round 4
// baseline (speedup 1.0000x reference)
#include <cuda_runtime.h>
#include <cuda_bf16.h>

#define D 128
#define MAXN 100000
#define BM 64
#define KC 32

// -------- device scratch (allocation-free rule: static __device__ arrays) --------
__device__ __align__(16) float g_h[(size_t)MAXN * D];     // x @ W
__device__ __align__(16) float g_agg[(size_t)MAXN * D];   // selfloop + b + res + scatter
__device__ __align__(16) float g_deg[MAXN];               // degree, then deg^{-1/2}
__device__ __align__(16) float g_sum[D];
__device__ __align__(16) float g_sumsq[D];
__device__ __align__(16) float g_scale[D];
__device__ __align__(16) float g_shift[D];
__device__ int g_is64;                                    // edge_index dtype flag

// index load: pos in [0, 2E); int64 mode reads lo word at 2*pos
__device__ __forceinline__ int ld_idx(const int* __restrict__ ei32, size_t pos, int is64) {
    return is64 ? ei32[pos << 1] : ei32[pos];
}

// -------- K0: init deg=1 (self loop), zero BN sums, assume int64 until disproven --------
__global__ void k_init(int N) {
    int i = blockIdx.x * blockDim.x + threadIdx.x;
    if (i < N) g_deg[i] = 1.0f;
    if (i < D) { g_sum[i] = 0.0f; g_sumsq[i] = 0.0f; }
    if (i == 0) g_is64 = 1;
}

// -------- K0b: detect dtype. If any hi-word of the first 1024 "int64" pairs is
// nonzero, the buffer is actually int32. --------
__global__ void k_detect(const int* __restrict__ ei32, int E) {
    int i = blockIdx.x * blockDim.x + threadIdx.x;   // 1024 threads
    if (i < E && i < 1024) {
        if (ei32[2 * i + 1] != 0) g_is64 = 0;        // racy but single value, benign
    }
}

// -------- K1: in-degree accumulate over dst --------
__global__ void k_deg(const int* __restrict__ ei32, int E) {
    int e = blockIdx.x * blockDim.x + threadIdx.x;
    if (e >= E) return;
    int is64 = g_is64;
    int d = ld_idx(ei32, (size_t)E + e, is64);
    atomicAdd(&g_deg[d], 1.0f);
}

// -------- K2: deg -> rsqrt(deg) in place (deg >= 1 always) --------
__global__ void k_dinv(int N) {
    int i = blockIdx.x * blockDim.x + threadIdx.x;
    if (i < N) g_deg[i] = rsqrtf(g_deg[i]);
}

// -------- K3: fused dual GEMM + epilogue, K-chunked, static smem (41KB) --------
// h = x@W ;  agg = h*dinv^2 + b + relu(x@res_W + res_b)
__global__ void __launch_bounds__(256) k_gemm(
    const float* __restrict__ x, const float* __restrict__ W,
    const float* __restrict__ b, const float* __restrict__ rW,
    const float* __restrict__ rb, int N)
{
    __shared__ float xs[BM][KC + 1];   // 64 x 33
    __shared__ float Ws[KC][D];        // 32 x 128
    __shared__ float Rs[KC][D];        // 32 x 128

    int tid = threadIdx.x;
    int row0 = blockIdx.x * BM;
    int tx = tid & 15;   // cols tx*8 .. tx*8+7
    int ty = tid >> 4;   // rows ty*4 .. ty*4+3

    float aW[4][8], aR[4][8];
    #pragma unroll
    for (int r = 0; r < 4; r++)
        #pragma unroll
        for (int c = 0; c < 8; c++) { aW[r][c] = 0.f; aR[r][c] = 0.f; }

    const float4* x4 = (const float4*)x;
    const float4* W4 = (const float4*)W;
    const float4* R4 = (const float4*)rW;

    for (int k0 = 0; k0 < D; k0 += KC) {
        __syncthreads();
        #pragma unroll
        for (int i = 0; i < 2; i++) {
            int lin = tid + i * 256;          // float4 slot; 8 per row
            int r = lin >> 3, c4 = lin & 7;
            int grow = row0 + r;
            float4 v = (grow < N) ? x4[(size_t)grow * 32 + (k0 >> 2) + c4]
                                  : make_float4(0.f, 0.f, 0.f, 0.f);
            float* p = &xs[r][c4 * 4];
            p[0] = v.x; p[1] = v.y; p[2] = v.z; p[3] = v.w;
        }
        #pragma unroll
        for (int i = 0; i < 4; i++) {
            int lin = tid + i * 256;          // 32 float4 per row
            int kr = lin >> 5, c4 = lin & 31;
            ((float4*)&Ws[kr][0])[c4] = W4[(size_t)(k0 + kr) * 32 + c4];
            ((float4*)&Rs[kr][0])[c4] = R4[(size_t)(k0 + kr) * 32 + c4];
        }
        __syncthreads();

        #pragma unroll 8
        for (int kk = 0; kk < KC; kk++) {
            float a[4];
            a[0] = xs[ty * 4 + 0][kk];
            a[1] = xs[ty * 4 + 1][kk];
            a[2] = xs[ty * 4 + 2][kk];
            a[3] = xs[ty * 4 + 3][kk];
            float4 w0 = *(const float4*)&Ws[kk][tx * 8];
            float4 w1 = *(const float4*)&Ws[kk][tx * 8 + 4];
            float4 r0 = *(const float4*)&Rs[kk][tx * 8];
            float4 r1 = *(const float4*)&Rs[kk][tx * 8 + 4];
            #pragma unroll
            for (int r = 0; r < 4; r++) {
                aW[r][0] += a[r] * w0.x; aW[r][1] += a[r] * w0.y;
                aW[r][2] += a[r] * w0.z; aW[r][3] += a[r] * w0.w;
                aW[r][4] += a[r] * w1.x; aW[r][5] += a[r] * w1.y;
                aW[r][6] += a[r] * w1.z; aW[r][7] += a[r] * w1.w;
                aR[r][0] += a[r] * r0.x; aR[r][1] += a[r] * r0.y;
                aR[r][2] += a[r] * r0.z; aR[r][3] += a[r] * r0.w;
                aR[r][4] += a[r] * r1.x; aR[r][5] += a[r] * r1.y;
                aR[r][6] += a[r] * r1.z; aR[r][7] += a[r] * r1.w;
            }
        }
    }

    #pragma unroll
    for (int r = 0; r < 4; r++) {
        int grow = row0 + ty * 4 + r;
        if (grow >= N) continue;
        float di = g_deg[grow];
        float n2 = di * di;
        #pragma unroll
        for (int c4 = 0; c4 < 2; c4++) {
            int col = tx * 8 + c4 * 4;
            float4 bb  = *(const float4*)(b + col);
            float4 rbb = *(const float4*)(rb + col);
            float4 hv;
            hv.x = aW[r][c4 * 4 + 0]; hv.y = aW[r][c4 * 4 + 1];
            hv.z = aW[r][c4 * 4 + 2]; hv.w = aW[r][c4 * 4 + 3];
            *(float4*)(g_h + (size_t)grow * D + col) = hv;
            float4 av;
            av.x = hv.x * n2 + bb.x + fmaxf(aR[r][c4 * 4 + 0] + rbb.x, 0.f);
            av.y = hv.y * n2 + bb.y + fmaxf(aR[r][c4 * 4 + 1] + rbb.y, 0.f);
            av.z = hv.z * n2 + bb.z + fmaxf(aR[r][c4 * 4 + 2] + rbb.z, 0.f);
            av.w = hv.w * n2 + bb.w + fmaxf(aR[r][c4 * 4 + 3] + rbb.w, 0.f);
            *(float4*)(g_agg + (size_t)grow * D + col) = av;
        }
    }
}

// -------- K4: edge scatter. Warp per edge, float4 gather, scalar atomic scatter --------
__global__ void k_scatter(const int* __restrict__ ei32, int E) {
    int gt = blockIdx.x * blockDim.x + threadIdx.x;
    int warp = gt >> 5;
    int lane = threadIdx.x & 31;
    if (warp >= E) return;
    int is64 = g_is64;
    int s = ld_idx(ei32, (size_t)warp, is64);
    int d = ld_idx(ei32, (size_t)E + warp, is64);
    float norm = g_deg[s] * g_deg[d];
    float4 v = *(const float4*)(g_h + (size_t)s * D + lane * 4);
    float* dst = g_agg + (size_t)d * D + lane * 4;
    atomicAdd(dst + 0, v.x * norm);
    atomicAdd(dst + 1, v.y * norm);
    atomicAdd(dst + 2, v.z * norm);
    atomicAdd(dst + 3, v.w * norm);
}

// -------- K5: BN column sums (float partials + float atomics) --------
__global__ void k_bnsum(int N) {
    int col = threadIdx.x;   // 128 threads
    float s = 0.f, sq = 0.f;
    for (int r = blockIdx.x; r < N; r += gridDim.x) {
        float v = g_agg[(size_t)r * D + col];
        s += v; sq += v * v;
    }
    atomicAdd(&g_sum[col], s);
    atomicAdd(&g_sumsq[col], sq);
}

// -------- K6: finalize BN scale/shift --------
__global__ void k_bnfin(const float* __restrict__ gamma,
                        const float* __restrict__ beta, int N) {
    int c = threadIdx.x;
    float inv_n = 1.0f / (float)N;
    float mean = g_sum[c] * inv_n;
    float var = fmaxf(g_sumsq[c] * inv_n - mean * mean, 0.0f);
    float sc = rsqrtf(var + 1e-5f) * gamma[c];
    g_scale[c] = sc;
    g_shift[c] = beta[c] - mean * sc;
}

// -------- K7: normalize to output --------
__global__ void k_norm(float* __restrict__ out, int N) {
    int idx = blockIdx.x * blockDim.x + threadIdx.x;   // float4 index
    int total = N * (D / 4);
    if (idx >= total) return;
    int colb = (idx & 31) * 4;
    float4 v  = ((const float4*)g_agg)[idx];
    float4 sc = *(const float4*)(g_scale + colb);
    float4 sh = *(const float4*)(g_shift + colb);
    float4 o;
    o.x = v.x * sc.x + sh.x;
    o.y = v.y * sc.y + sh.y;
    o.z = v.z * sc.z + sh.z;
    o.w = v.w * sc.w + sh.w;
    ((float4*)out)[idx] = o;
}

extern "C" void kernel_launch(void* const* d_in, const int* in_sizes, int n_in,
                              void* d_out, int out_size) {
    const float* x     = (const float*)d_in[0];
    const int*   ei32  = (const int*)d_in[1];     // int32 OR int64 (auto-detected)
    const float* W     = (const float*)d_in[2];
    const float* b     = (const float*)d_in[3];
    const float* rW    = (const float*)d_in[4];
    const float* rb    = (const float*)d_in[5];
    const float* gamma = (const float*)d_in[6];
    const float* beta  = (const float*)d_in[7];
    float* out = (float*)d_out;

    int N = in_sizes[0] / D;
    int E = in_sizes[1] / 2;   // element count is dtype-independent (2 x E elements)

    k_init<<<(N + 255) / 256, 256>>>(N);
    k_detect<<<4, 256>>>(ei32, E);
    k_deg<<<(E + 255) / 256, 256>>>(ei32, E);
    k_dinv<<<(N + 255) / 256, 256>>>(N);
    k_gemm<<<(N + BM - 1) / BM, 256>>>(x, W, b, rW, rb, N);
    k_scatter<<<(E + 7) / 8, 256>>>(ei32, E);
    k_bnsum<<<512, 128>>>(N);
    k_bnfin<<<1, 128>>>(gamma, beta, N);
    k_norm<<<(N * (D / 4) + 255) / 256, 256>>>(out, N);
}

// round 5
// speedup vs baseline: 1.1967x; 1.1967x over previous
#include <cuda_runtime.h>
#include <cuda_bf16.h>

#define D 128
#define MAXN 100000
#define BM 64
#define KC 32

// -------- device scratch (allocation-free rule: static __device__ arrays) --------
__device__ __align__(16) float g_h[(size_t)MAXN * D];     // x @ W
__device__ __align__(16) float g_agg[(size_t)MAXN * D];   // selfloop + b + res + scatter
__device__ __align__(16) float g_deg[MAXN];               // degree, then deg^{-1/2}
__device__ __align__(16) float g_sum[D];
__device__ __align__(16) float g_sumsq[D];
__device__ __align__(16) float g_scale[D];
__device__ __align__(16) float g_shift[D];
__device__ int g_is64;                                    // edge_index dtype flag

// index load: pos in [0, 2E); int64 mode reads lo word at 2*pos
__device__ __forceinline__ int ld_idx(const int* __restrict__ ei32, size_t pos, int is64) {
    return is64 ? ei32[pos << 1] : ei32[pos];
}

// -------- K0: init deg=1 (self loop), zero BN sums, assume int64 until disproven --------
__global__ void k_init(int N) {
    int i = blockIdx.x * blockDim.x + threadIdx.x;
    if (i < N) g_deg[i] = 1.0f;
    if (i < D) { g_sum[i] = 0.0f; g_sumsq[i] = 0.0f; }
    if (i == 0) g_is64 = 1;
}

// -------- K0b: detect dtype --------
__global__ void k_detect(const int* __restrict__ ei32, int E) {
    int i = blockIdx.x * blockDim.x + threadIdx.x;   // 1024 threads
    if (i < E && i < 1024) {
        if (ei32[2 * i + 1] != 0) g_is64 = 0;        // racy but single value, benign
    }
}

// -------- K1: in-degree accumulate over dst --------
__global__ void k_deg(const int* __restrict__ ei32, int E) {
    int e = blockIdx.x * blockDim.x + threadIdx.x;
    if (e >= E) return;
    int is64 = g_is64;
    int d = ld_idx(ei32, (size_t)E + e, is64);
    atomicAdd(&g_deg[d], 1.0f);
}

// -------- K2: deg -> rsqrt(deg) in place (deg >= 1 always) --------
__global__ void k_dinv(int N) {
    int i = blockIdx.x * blockDim.x + threadIdx.x;
    if (i < N) g_deg[i] = rsqrtf(g_deg[i]);
}

// -------- K3: fused dual GEMM + epilogue, K-chunked, static smem (41KB) --------
// h = x@W ;  agg = h*dinv^2 + b + relu(x@res_W + res_b)
__global__ void __launch_bounds__(256) k_gemm(
    const float* __restrict__ x, const float* __restrict__ W,
    const float* __restrict__ b, const float* __restrict__ rW,
    const float* __restrict__ rb, int N)
{
    __shared__ float xs[BM][KC + 1];   // 64 x 33
    __shared__ float Ws[KC][D];        // 32 x 128
    __shared__ float Rs[KC][D];        // 32 x 128

    int tid = threadIdx.x;
    int row0 = blockIdx.x * BM;
    int tx = tid & 15;   // cols tx*8 .. tx*8+7
    int ty = tid >> 4;   // rows ty*4 .. ty*4+3

    float aW[4][8], aR[4][8];
    #pragma unroll
    for (int r = 0; r < 4; r++)
        #pragma unroll
        for (int c = 0; c < 8; c++) { aW[r][c] = 0.f; aR[r][c] = 0.f; }

    const float4* x4 = (const float4*)x;
    const float4* W4 = (const float4*)W;
    const float4* R4 = (const float4*)rW;

    for (int k0 = 0; k0 < D; k0 += KC) {
        __syncthreads();
        #pragma unroll
        for (int i = 0; i < 2; i++) {
            int lin = tid + i * 256;          // float4 slot; 8 per row
            int r = lin >> 3, c4 = lin & 7;
            int grow = row0 + r;
            float4 v = (grow < N) ? x4[(size_t)grow * 32 + (k0 >> 2) + c4]
                                  : make_float4(0.f, 0.f, 0.f, 0.f);
            float* p = &xs[r][c4 * 4];
            p[0] = v.x; p[1] = v.y; p[2] = v.z; p[3] = v.w;
        }
        #pragma unroll
        for (int i = 0; i < 4; i++) {
            int lin = tid + i * 256;          // 32 float4 per row
            int kr = lin >> 5, c4 = lin & 31;
            ((float4*)&Ws[kr][0])[c4] = W4[(size_t)(k0 + kr) * 32 + c4];
            ((float4*)&Rs[kr][0])[c4] = R4[(size_t)(k0 + kr) * 32 + c4];
        }
        __syncthreads();

        #pragma unroll 8
        for (int kk = 0; kk < KC; kk++) {
            float a[4];
            a[0] = xs[ty * 4 + 0][kk];
            a[1] = xs[ty * 4 + 1][kk];
            a[2] = xs[ty * 4 + 2][kk];
            a[3] = xs[ty * 4 + 3][kk];
            float4 w0 = *(const float4*)&Ws[kk][tx * 8];
            float4 w1 = *(const float4*)&Ws[kk][tx * 8 + 4];
            float4 r0 = *(const float4*)&Rs[kk][tx * 8];
            float4 r1 = *(const float4*)&Rs[kk][tx * 8 + 4];
            #pragma unroll
            for (int r = 0; r < 4; r++) {
                aW[r][0] += a[r] * w0.x; aW[r][1] += a[r] * w0.y;
                aW[r][2] += a[r] * w0.z; aW[r][3] += a[r] * w0.w;
                aW[r][4] += a[r] * w1.x; aW[r][5] += a[r] * w1.y;
                aW[r][6] += a[r] * w1.z; aW[r][7] += a[r] * w1.w;
                aR[r][0] += a[r] * r0.x; aR[r][1] += a[r] * r0.y;
                aR[r][2] += a[r] * r0.z; aR[r][3] += a[r] * r0.w;
                aR[r][4] += a[r] * r1.x; aR[r][5] += a[r] * r1.y;
                aR[r][6] += a[r] * r1.z; aR[r][7] += a[r] * r1.w;
            }
        }
    }

    #pragma unroll
    for (int r = 0; r < 4; r++) {
        int grow = row0 + ty * 4 + r;
        if (grow >= N) continue;
        float di = g_deg[grow];
        float n2 = di * di;
        #pragma unroll
        for (int c4 = 0; c4 < 2; c4++) {
            int col = tx * 8 + c4 * 4;
            float4 bb  = *(const float4*)(b + col);
            float4 rbb = *(const float4*)(rb + col);
            float4 hv;
            hv.x = aW[r][c4 * 4 + 0]; hv.y = aW[r][c4 * 4 + 1];
            hv.z = aW[r][c4 * 4 + 2]; hv.w = aW[r][c4 * 4 + 3];
            *(float4*)(g_h + (size_t)grow * D + col) = hv;
            float4 av;
            av.x = hv.x * n2 + bb.x + fmaxf(aR[r][c4 * 4 + 0] + rbb.x, 0.f);
            av.y = hv.y * n2 + bb.y + fmaxf(aR[r][c4 * 4 + 1] + rbb.y, 0.f);
            av.z = hv.z * n2 + bb.z + fmaxf(aR[r][c4 * 4 + 2] + rbb.z, 0.f);
            av.w = hv.w * n2 + bb.w + fmaxf(aR[r][c4 * 4 + 3] + rbb.w, 0.f);
            *(float4*)(g_agg + (size_t)grow * D + col) = av;
        }
    }
}

// -------- K4: edge scatter. Warp per edge, float4 gather, v4 REDG scatter --------
// red.global.add.v4.f32 with explicit cvta.to.global (vector red is .global-only).
__global__ void k_scatter(const int* __restrict__ ei32, int E) {
    int gt = blockIdx.x * blockDim.x + threadIdx.x;
    int warp = gt >> 5;
    int lane = threadIdx.x & 31;
    if (warp >= E) return;
    int is64 = g_is64;
    int s = ld_idx(ei32, (size_t)warp, is64);
    int d = ld_idx(ei32, (size_t)E + warp, is64);
    float norm = g_deg[s] * g_deg[d];
    float4 v = *(const float4*)(g_h + (size_t)s * D + lane * 4);
    v.x *= norm; v.y *= norm; v.z *= norm; v.w *= norm;
    float* dst = g_agg + (size_t)d * D + lane * 4;
    asm volatile(
        "{ .reg .u64 pg;\n\t"
        "  cvta.to.global.u64 pg, %0;\n\t"
        "  red.global.add.v4.f32 [pg], {%1, %2, %3, %4}; }"
        :: "l"(dst), "f"(v.x), "f"(v.y), "f"(v.z), "f"(v.w)
        : "memory");
}

// -------- K5: BN column sums (float partials + float atomics) --------
__global__ void k_bnsum(int N) {
    int col = threadIdx.x;   // 128 threads
    float s = 0.f, sq = 0.f;
    for (int r = blockIdx.x; r < N; r += gridDim.x) {
        float v = g_agg[(size_t)r * D + col];
        s += v; sq += v * v;
    }
    atomicAdd(&g_sum[col], s);
    atomicAdd(&g_sumsq[col], sq);
}

// -------- K6: finalize BN scale/shift --------
__global__ void k_bnfin(const float* __restrict__ gamma,
                        const float* __restrict__ beta, int N) {
    int c = threadIdx.x;
    float inv_n = 1.0f / (float)N;
    float mean = g_sum[c] * inv_n;
    float var = fmaxf(g_sumsq[c] * inv_n - mean * mean, 0.0f);
    float sc = rsqrtf(var + 1e-5f) * gamma[c];
    g_scale[c] = sc;
    g_shift[c] = beta[c] - mean * sc;
}

// -------- K7: normalize to output --------
__global__ void k_norm(float* __restrict__ out, int N) {
    int idx = blockIdx.x * blockDim.x + threadIdx.x;   // float4 index
    int total = N * (D / 4);
    if (idx >= total) return;
    int colb = (idx & 31) * 4;
    float4 v  = ((const float4*)g_agg)[idx];
    float4 sc = *(const float4*)(g_scale + colb);
    float4 sh = *(const float4*)(g_shift + colb);
    float4 o;
    o.x = v.x * sc.x + sh.x;
    o.y = v.y * sc.y + sh.y;
    o.z = v.z * sc.z + sh.z;
    o.w = v.w * sc.w + sh.w;
    ((float4*)out)[idx] = o;
}

extern "C" void kernel_launch(void* const* d_in, const int* in_sizes, int n_in,
                              void* d_out, int out_size) {
    const float* x     = (const float*)d_in[0];
    const int*   ei32  = (const int*)d_in[1];     // int32 OR int64 (auto-detected)
    const float* W     = (const float*)d_in[2];
    const float* b     = (const float*)d_in[3];
    const float* rW    = (const float*)d_in[4];
    const float* rb    = (const float*)d_in[5];
    const float* gamma = (const float*)d_in[6];
    const float* beta  = (const float*)d_in[7];
    float* out = (float*)d_out;

    int N = in_sizes[0] / D;
    int E = in_sizes[1] / 2;   // element count is dtype-independent (2 x E elements)

    k_init<<<(N + 255) / 256, 256>>>(N);
    k_detect<<<4, 256>>>(ei32, E);
    k_deg<<<(E + 255) / 256, 256>>>(ei32, E);
    k_dinv<<<(N + 255) / 256, 256>>>(N);
    k_gemm<<<(N + BM - 1) / BM, 256>>>(x, W, b, rW, rb, N);
    k_scatter<<<(E + 7) / 8, 256>>>(ei32, E);
    k_bnsum<<<512, 128>>>(N);
    k_bnfin<<<1, 128>>>(gamma, beta, N);
    k_norm<<<(N * (D / 4) + 255) / 256, 256>>>(out, N);
}